// round 5
// baseline (speedup 1.0000x reference)
#include <cuda_runtime.h>

// ============================================================================
// TransformerEncoderLayer: B=4, S=4096, D=1024, 8 heads (head-local attention)
//
//   q = x@Wq+bq; k = x@Wk+bk; v = x@Wv+bv            (3 GEMMs 16384x1024x1024)
//   per token: scores[h][t] = q[h]·k[t]/sqrt(128); softmax over t; out = attn@v
//   ff = relu(out@W1+b1)@W2+b2                        (2 GEMMs)
//   outputs: ff [16384*1024] then attn_weights [16384*64] (if out_size holds it)
// ============================================================================

#define BM 128
#define BN 128
#define BK 8

static const int M_TOK  = 16384;   // B*S
static const int DMODEL = 1024;

// Scratch (allocation-free rule: __device__ globals)
__device__ float g_q [16384 * 1024];
__device__ float g_k [16384 * 1024];
__device__ float g_v [16384 * 1024];
__device__ float g_ao[16384 * 1024];
__device__ float g_h [16384 * 1024];

// ----------------------------------------------------------------------------
// SGEMM: C[M,N] = A[M,K] @ B[K,N] + bias[N]  (optional ReLU)
// 128x128 block tile, BK=8, 256 threads, 8x8 per-thread microtile (4+4 split),
// double-buffered shared memory. Requires M%128==0, N%128==0, K%8==0.
// ----------------------------------------------------------------------------
__global__ __launch_bounds__(256, 2)
void sgemm_bias_kernel(const float* __restrict__ A, const float* __restrict__ B,
                       const float* __restrict__ bias, float* __restrict__ C,
                       int M, int N, int K, int relu)
{
    __shared__ float As[2][BK][BM];
    __shared__ float Bs[2][BK][BN];

    const int tid  = threadIdx.x;
    const int row0 = blockIdx.y * BM;
    const int col0 = blockIdx.x * BN;

    // Global-load assignment (one float4 per thread per tile per operand)
    const int a_row = tid >> 1;          // 0..127
    const int a_col = (tid & 1) << 2;    // 0 or 4
    const int b_row = tid >> 5;          // 0..7
    const int b_col = (tid & 31) << 2;   // 0..124

    const float* Aptr = A + (size_t)(row0 + a_row) * K + a_col;
    const float* Bptr = B + (size_t)b_row * N + col0 + b_col;

    // Microtile mapping: rows {ty*4+i, 64+ty*4+i}, cols {tx*4+j, 64+tx*4+j}
    const int tx = tid & 15;
    const int ty = tid >> 4;

    float acc[8][8];
    #pragma unroll
    for (int i = 0; i < 8; i++)
        #pragma unroll
        for (int j = 0; j < 8; j++) acc[i][j] = 0.0f;

    // Preload tile 0 into buffer 0
    float4 a_reg = *(const float4*)(Aptr);
    float4 b_reg = *(const float4*)(Bptr);
    As[0][a_col + 0][a_row] = a_reg.x;
    As[0][a_col + 1][a_row] = a_reg.y;
    As[0][a_col + 2][a_row] = a_reg.z;
    As[0][a_col + 3][a_row] = a_reg.w;
    *(float4*)&Bs[0][b_row][b_col] = b_reg;
    __syncthreads();

    const int nt = K / BK;
    for (int t = 0; t < nt; ++t) {
        const int cur = t & 1;

        // Prefetch next tile (gmem -> regs) while computing current
        if (t + 1 < nt) {
            a_reg = *(const float4*)(Aptr + (t + 1) * BK);
            b_reg = *(const float4*)(Bptr + (size_t)(t + 1) * BK * N);
        }

        #pragma unroll
        for (int k = 0; k < BK; ++k) {
            float af[8], bf[8];
            *(float4*)(af)     = *(const float4*)&As[cur][k][ty * 4];
            *(float4*)(af + 4) = *(const float4*)&As[cur][k][64 + ty * 4];
            *(float4*)(bf)     = *(const float4*)&Bs[cur][k][tx * 4];
            *(float4*)(bf + 4) = *(const float4*)&Bs[cur][k][64 + tx * 4];
            #pragma unroll
            for (int i = 0; i < 8; i++)
                #pragma unroll
                for (int j = 0; j < 8; j++)
                    acc[i][j] += af[i] * bf[j];
        }

        if (t + 1 < nt) {
            const int nx = cur ^ 1;
            As[nx][a_col + 0][a_row] = a_reg.x;
            As[nx][a_col + 1][a_row] = a_reg.y;
            As[nx][a_col + 2][a_row] = a_reg.z;
            As[nx][a_col + 3][a_row] = a_reg.w;
            *(float4*)&Bs[nx][b_row][b_col] = b_reg;
            __syncthreads();
        }
    }

    // Epilogue: bias (+ ReLU), vectorized float4 stores
    #pragma unroll
    for (int ii = 0; ii < 2; ii++) {
        #pragma unroll
        for (int i = 0; i < 4; i++) {
            const int row = row0 + ii * 64 + ty * 4 + i;
            #pragma unroll
            for (int jj = 0; jj < 2; jj++) {
                const int col = col0 + jj * 64 + tx * 4;
                const float4 bb = *(const float4*)(bias + col);
                float4 r;
                r.x = acc[ii * 4 + i][jj * 4 + 0] + bb.x;
                r.y = acc[ii * 4 + i][jj * 4 + 1] + bb.y;
                r.z = acc[ii * 4 + i][jj * 4 + 2] + bb.z;
                r.w = acc[ii * 4 + i][jj * 4 + 3] + bb.w;
                if (relu) {
                    r.x = fmaxf(r.x, 0.0f);
                    r.y = fmaxf(r.y, 0.0f);
                    r.z = fmaxf(r.z, 0.0f);
                    r.w = fmaxf(r.w, 0.0f);
                }
                *(float4*)(C + (size_t)row * N + col) = r;
            }
        }
    }
}

// ----------------------------------------------------------------------------
// Per-token head attention: one block (128 threads) per token.
// q,k,v are [8 heads][128 dims] slices of the same token position.
// scores[h][t] = q[h]·k[t] / sqrt(128); softmax over t; out[h] = sum_t w*v[t]
// ----------------------------------------------------------------------------
__global__ void attn_kernel(const float* __restrict__ Q, const float* __restrict__ K,
                            const float* __restrict__ V, float* __restrict__ O,
                            float* __restrict__ AW)
{
    __shared__ float sq[8 * 132];   // padded stride 132 -> conflict-free
    __shared__ float sk[8 * 132];
    __shared__ float sv[8 * 132];
    __shared__ float sw[64];

    const int tid = threadIdx.x;
    const size_t base = (size_t)blockIdx.x * 1024;

    for (int i = tid; i < 1024; i += 128) {
        const int h = i >> 7, d = i & 127;
        sq[h * 132 + d] = Q[base + i];
        sk[h * 132 + d] = K[base + i];
        sv[h * 132 + d] = V[base + i];
    }
    __syncthreads();

    if (tid < 64) {
        const int h = tid >> 3, t = tid & 7;
        float s = 0.0f;
        #pragma unroll 8
        for (int d = 0; d < 128; d++)
            s += sq[h * 132 + d] * sk[t * 132 + d];
        sw[tid] = s * 0.08838834764831845f;   // 1/sqrt(128)
    }
    __syncthreads();

    if (tid < 8) {
        const int h = tid;
        float m = sw[h * 8];
        #pragma unroll
        for (int t = 1; t < 8; t++) m = fmaxf(m, sw[h * 8 + t]);
        float e[8], sum = 0.0f;
        #pragma unroll
        for (int t = 0; t < 8; t++) { e[t] = expf(sw[h * 8 + t] - m); sum += e[t]; }
        const float inv = 1.0f / sum;
        #pragma unroll
        for (int t = 0; t < 8; t++) sw[h * 8 + t] = e[t] * inv;
    }
    __syncthreads();

    const int d = tid;  // 0..127
    #pragma unroll
    for (int h = 0; h < 8; h++) {
        float o = 0.0f;
        #pragma unroll
        for (int t = 0; t < 8; t++)
            o += sw[h * 8 + t] * sv[t * 132 + d];
        O[base + h * 128 + d] = o;
    }

    if (AW != nullptr && tid < 64)
        AW[(size_t)blockIdx.x * 64 + tid] = sw[tid];   // [.., h, t] layout
}

// ----------------------------------------------------------------------------
extern "C" void kernel_launch(void* const* d_in, const int* in_sizes, int n_in,
                              void* d_out, int out_size)
{
    (void)in_sizes; (void)n_in;
    const float* x  = (const float*)d_in[0];
    const float* Wq = (const float*)d_in[1];
    const float* bq = (const float*)d_in[2];
    const float* Wk = (const float*)d_in[3];
    const float* bk = (const float*)d_in[4];
    const float* Wv = (const float*)d_in[5];
    const float* bv = (const float*)d_in[6];
    const float* W1 = (const float*)d_in[7];
    const float* b1 = (const float*)d_in[8];
    const float* W2 = (const float*)d_in[9];
    const float* b2 = (const float*)d_in[10];
    float* out = (float*)d_out;

    float *q, *k, *v, *ao, *h;
    cudaGetSymbolAddress((void**)&q,  g_q);
    cudaGetSymbolAddress((void**)&k,  g_k);
    cudaGetSymbolAddress((void**)&v,  g_v);
    cudaGetSymbolAddress((void**)&ao, g_ao);
    cudaGetSymbolAddress((void**)&h,  g_h);

    const int ff_elems   = M_TOK * DMODEL;      // 16,777,216
    const int attn_elems = M_TOK * 64;          // 1,048,576
    float* aw = (out_size >= ff_elems + attn_elems) ? (out + ff_elems) : nullptr;

    dim3 grid(DMODEL / BN, M_TOK / BM);         // (8, 128)
    dim3 block(256);

    sgemm_bias_kernel<<<grid, block>>>(x,  Wq, bq, q,  M_TOK, DMODEL, DMODEL, 0);
    sgemm_bias_kernel<<<grid, block>>>(x,  Wk, bk, k,  M_TOK, DMODEL, DMODEL, 0);
    sgemm_bias_kernel<<<grid, block>>>(x,  Wv, bv, v,  M_TOK, DMODEL, DMODEL, 0);

    attn_kernel<<<M_TOK, 128>>>(q, k, v, ao, aw);

    sgemm_bias_kernel<<<grid, block>>>(ao, W1, b1, h,   M_TOK, DMODEL, DMODEL, 1);
    sgemm_bias_kernel<<<grid, block>>>(h,  W2, b2, out, M_TOK, DMODEL, DMODEL, 0);
}

// round 7
// speedup vs baseline: 2.4234x; 2.4234x over previous
#include <cuda_runtime.h>
#include <cuda_bf16.h>
#include <cstdint>

// ============================================================================
// TransformerEncoderLayer (B=4,S=4096,D=1024, 8 local heads) on sm_103 (base
// target: no tcgen05). GEMMs use mma.sync.m16n8k16 bf16 with a 3-product
// double-bf16 split (hi*hi + hi*lo + lo*hi), fp32 accumulation.
//   q/k/v = x@W+b (fp32 out) -> per-token 8x8 head attention (fp32,
//   emits bf16 hi/lo) -> h = relu(ao@W1+b1) (bf16 hi/lo) -> out = h@W2+b2.
// ============================================================================

static const int M_TOK = 16384;
static const int DM    = 1024;

// ---------------- scratch (__device__ globals; allocation-free rule) --------
__device__ float g_q[16384 * 1024];
__device__ float g_k[16384 * 1024];
__device__ float g_v[16384 * 1024];
__device__ __nv_bfloat16 g_xhi [16384 * 1024];
__device__ __nv_bfloat16 g_xlo [16384 * 1024];
__device__ __nv_bfloat16 g_aohi[16384 * 1024];
__device__ __nv_bfloat16 g_aolo[16384 * 1024];
__device__ __nv_bfloat16 g_hhi [16384 * 1024];
__device__ __nv_bfloat16 g_hlo [16384 * 1024];
__device__ __nv_bfloat16 g_wthi[5][1024 * 1024];   // W^T hi  [n][k]
__device__ __nv_bfloat16 g_wtlo[5][1024 * 1024];   // W^T lo  [n][k]

// ---------------- PTX helpers (all sm_80-level: valid on sm_103 base) -------
__device__ __forceinline__ uint32_t smem_u32(const void* p) {
    uint32_t a;
    asm("{ .reg .u64 t; cvta.to.shared.u64 t, %1; cvt.u32.u64 %0, t; }"
        : "=r"(a) : "l"(p));
    return a;
}
__device__ __forceinline__ void cpasync16(uint32_t saddr, const void* g) {
    asm volatile("cp.async.cg.shared.global [%0], [%1], 16;"
                 :: "r"(saddr), "l"(g));
}
#define CP_COMMIT() asm volatile("cp.async.commit_group;" ::: "memory")
#define CP_WAIT1()  asm volatile("cp.async.wait_group 1;" ::: "memory")

__device__ __forceinline__ void ldsm4(uint32_t r[4], uint32_t addr) {
    asm volatile("ldmatrix.sync.aligned.m8n8.x4.shared.b16 {%0,%1,%2,%3}, [%4];"
                 : "=r"(r[0]), "=r"(r[1]), "=r"(r[2]), "=r"(r[3]) : "r"(addr));
}
__device__ __forceinline__ void mma16816(float c[4], const uint32_t a[4],
                                         uint32_t b0, uint32_t b1) {
    asm volatile(
        "mma.sync.aligned.m16n8k16.row.col.f32.bf16.bf16.f32 "
        "{%0,%1,%2,%3}, {%4,%5,%6,%7}, {%8,%9}, {%0,%1,%2,%3};"
        : "+f"(c[0]), "+f"(c[1]), "+f"(c[2]), "+f"(c[3])
        : "r"(a[0]), "r"(a[1]), "r"(a[2]), "r"(a[3]), "r"(b0), "r"(b1));
}

__device__ __forceinline__ uint32_t pack_hi_lo(float x, float y, uint32_t& lo_out) {
    const __nv_bfloat16 hx = __float2bfloat16(x);
    const __nv_bfloat16 hy = __float2bfloat16(y);
    const __nv_bfloat16 lx = __float2bfloat16(x - __bfloat162float(hx));
    const __nv_bfloat16 ly = __float2bfloat16(y - __bfloat162float(hy));
    union { __nv_bfloat16 b[2]; uint32_t u; } h, l;
    h.b[0] = hx; h.b[1] = hy; l.b[0] = lx; l.b[1] = ly;
    lo_out = l.u;
    return h.u;
}

// smem: 3 stages x 64KB; stage = Ahi@0, Alo@16K, Bhi@32K, Blo@48K,
// each operand 128 rows x 128B (BK=64 bf16), SW128 swizzle.
static const int SMEM_DYN = 3 * 65536;

// ============================================================================
// GEMM D[16384 x 1024] = A @ W + bias. A split (hi,lo) row-major [m][k],
// W^T split (hi,lo) [n][k]. Out: fp32 Cf and/or bf16 split (Chi,Clo). relu opt.
// ============================================================================
__global__ __launch_bounds__(256, 1)
void gemm_mma_bf16x3(const __nv_bfloat16* __restrict__ Ahi, const __nv_bfloat16* __restrict__ Alo,
                     const __nv_bfloat16* __restrict__ Bhi, const __nv_bfloat16* __restrict__ Blo,
                     const float* __restrict__ bias,
                     float* __restrict__ Cf,
                     __nv_bfloat16* __restrict__ Chi, __nv_bfloat16* __restrict__ Clo,
                     int relu)
{
    extern __shared__ char smem[];
    const uint32_t sbase = smem_u32(smem);
    const int tid  = threadIdx.x;
    const int lane = tid & 31;
    const int wid  = tid >> 5;
    const int wm   = wid >> 2;          // 0..1  (m: 64 each)
    const int wn   = wid & 3;           // 0..3  (n: 32 each)
    const int m0   = blockIdx.y * 128;
    const int n0   = blockIdx.x * 128;

    float acc[4][4][4];
    #pragma unroll
    for (int a = 0; a < 4; ++a)
        #pragma unroll
        for (int n = 0; n < 4; ++n)
            #pragma unroll
            for (int e = 0; e < 4; ++e) acc[a][n][e] = 0.0f;

    // ---- gmem->smem mapping: 8 threads per 128B row, all 8 granules -------
    const int lrow = tid >> 3;                  // 0..31, + j*32
    const int lc   = tid & 7;                   // 16B granule
    auto issue_tile = [&](int t) {
        const uint32_t st = sbase + (uint32_t)(t % 3) * 65536u;
        const int kt = t * 64;
        #pragma unroll
        for (int j = 0; j < 4; ++j) {
            const int row = j * 32 + lrow;
            const uint32_t so = (uint32_t)row * 128u +
                                (((uint32_t)lc * 16u) ^ (((uint32_t)row & 7u) << 4));
            const size_t ga = (size_t)(m0 + row) * 1024 + kt + lc * 8;
            const size_t gb = (size_t)(n0 + row) * 1024 + kt + lc * 8;
            cpasync16(st +          so, Ahi + ga);
            cpasync16(st + 16384u + so, Alo + ga);
            cpasync16(st + 32768u + so, Bhi + gb);
            cpasync16(st + 49152u + so, Blo + gb);
        }
    };

    // ---- ldmatrix per-thread constants -------------------------------------
    const int mi = lane >> 3, li = lane & 7;
    const uint32_t axor  = ((uint32_t)li) << 4;                 // swizzle xor
    const int      arow0 = wm * 64 + ((mi & 1) << 3) + li;      // + a*16
    const uint32_t acb0  = ((uint32_t)(mi >> 1)) << 4;          // + ks*32
    const int      brow0 = wn * 32 + ((mi >> 1) << 3) + li;     // + g*16
    const uint32_t bcb0  = ((uint32_t)(mi & 1)) << 4;           // + ks*32

    // ---- pipeline: 3-stage cp.async ---------------------------------------
    issue_tile(0); CP_COMMIT();
    issue_tile(1); CP_COMMIT();

    for (int t = 0; t < 16; ++t) {
        CP_WAIT1();
        __syncthreads();
        if (t + 2 < 16) issue_tile(t + 2);
        CP_COMMIT();

        const uint32_t st = sbase + (uint32_t)(t % 3) * 65536u;
        #pragma unroll
        for (int ks = 0; ks < 4; ++ks) {
            const uint32_t kc = (uint32_t)ks * 32u;
            uint32_t aH[4][4], aL[4][4], bH[2][4], bL[2][4];

            #pragma unroll
            for (int a = 0; a < 4; ++a)
                ldsm4(aH[a], st + (uint32_t)(arow0 + a * 16) * 128u + ((kc + acb0) ^ axor));
            #pragma unroll
            for (int g = 0; g < 2; ++g)
                ldsm4(bH[g], st + 32768u + (uint32_t)(brow0 + g * 16) * 128u + ((kc + bcb0) ^ axor));
            #pragma unroll
            for (int a = 0; a < 4; ++a)
                #pragma unroll
                for (int n = 0; n < 4; ++n)
                    mma16816(acc[a][n], aH[a], bH[n >> 1][(n & 1) * 2], bH[n >> 1][(n & 1) * 2 + 1]);

            #pragma unroll
            for (int g = 0; g < 2; ++g)
                ldsm4(bL[g], st + 49152u + (uint32_t)(brow0 + g * 16) * 128u + ((kc + bcb0) ^ axor));
            #pragma unroll
            for (int a = 0; a < 4; ++a)
                #pragma unroll
                for (int n = 0; n < 4; ++n)
                    mma16816(acc[a][n], aH[a], bL[n >> 1][(n & 1) * 2], bL[n >> 1][(n & 1) * 2 + 1]);

            #pragma unroll
            for (int a = 0; a < 4; ++a)
                ldsm4(aL[a], st + 16384u + (uint32_t)(arow0 + a * 16) * 128u + ((kc + acb0) ^ axor));
            #pragma unroll
            for (int a = 0; a < 4; ++a)
                #pragma unroll
                for (int n = 0; n < 4; ++n)
                    mma16816(acc[a][n], aL[a], bH[n >> 1][(n & 1) * 2], bH[n >> 1][(n & 1) * 2 + 1]);
        }
    }

    // ---- epilogue ----------------------------------------------------------
    const int er0 = m0 + wm * 64 + (lane >> 2);
    const int ec0 = n0 + wn * 32 + (lane & 3) * 2;
    #pragma unroll
    for (int a = 0; a < 4; ++a) {
        #pragma unroll
        for (int n = 0; n < 4; ++n) {
            const int r0 = er0 + a * 16, r1 = r0 + 8;
            const int c  = ec0 + n * 8;
            const float b0 = __ldg(bias + c), b1 = __ldg(bias + c + 1);
            float v00 = acc[a][n][0] + b0, v01 = acc[a][n][1] + b1;
            float v10 = acc[a][n][2] + b0, v11 = acc[a][n][3] + b1;
            if (relu) {
                v00 = fmaxf(v00, 0.0f); v01 = fmaxf(v01, 0.0f);
                v10 = fmaxf(v10, 0.0f); v11 = fmaxf(v11, 0.0f);
            }
            if (Cf) {
                *(float2*)(Cf + (size_t)r0 * 1024 + c) = make_float2(v00, v01);
                *(float2*)(Cf + (size_t)r1 * 1024 + c) = make_float2(v10, v11);
            }
            if (Chi) {
                uint32_t l0, l1;
                const uint32_t h0 = pack_hi_lo(v00, v01, l0);
                const uint32_t h1 = pack_hi_lo(v10, v11, l1);
                *(uint32_t*)(Chi + (size_t)r0 * 1024 + c) = h0;
                *(uint32_t*)(Clo + (size_t)r0 * 1024 + c) = l0;
                *(uint32_t*)(Chi + (size_t)r1 * 1024 + c) = h1;
                *(uint32_t*)(Clo + (size_t)r1 * 1024 + c) = l1;
            }
        }
    }
}

// ============================================================================
// fp32 -> bf16 hi/lo elementwise split (for x)
// ============================================================================
__global__ void split_kernel(const float* __restrict__ X,
                             __nv_bfloat16* __restrict__ H,
                             __nv_bfloat16* __restrict__ L, int n4)
{
    const int i = blockIdx.x * blockDim.x + threadIdx.x;
    if (i >= n4) return;
    const float4 v = ((const float4*)X)[i];
    const float vv[4] = {v.x, v.y, v.z, v.w};
    union { __nv_bfloat16 b[4]; uint2 u; } hh, ll;
    #pragma unroll
    for (int e = 0; e < 4; ++e) {
        const __nv_bfloat16 hb = __float2bfloat16(vv[e]);
        hh.b[e] = hb;
        ll.b[e] = __float2bfloat16(vv[e] - __bfloat162float(hb));
    }
    ((uint2*)H)[i] = hh.u;
    ((uint2*)L)[i] = ll.u;
}

// ============================================================================
// W [k][n] fp32 -> W^T hi/lo [n][k] bf16 (tiled transpose + split)
// ============================================================================
__global__ void wconvert_kernel(const float* __restrict__ W,
                                __nv_bfloat16* __restrict__ Thi,
                                __nv_bfloat16* __restrict__ Tlo)
{
    __shared__ float t[32][33];
    const int k0 = blockIdx.y * 32, n0 = blockIdx.x * 32;
    const int tx = threadIdx.x, ty = threadIdx.y;  // 32 x 8
    #pragma unroll
    for (int i = 0; i < 4; ++i)
        t[ty + i*8][tx] = W[(size_t)(k0 + ty + i*8) * 1024 + n0 + tx];
    __syncthreads();
    #pragma unroll
    for (int i = 0; i < 4; ++i) {
        const float v = t[tx][ty + i*8];           // = W[k0+tx][n0+ty+i*8]
        const size_t o = (size_t)(n0 + ty + i*8) * 1024 + k0 + tx;
        const __nv_bfloat16 hb = __float2bfloat16(v);
        Thi[o] = hb;
        Tlo[o] = __float2bfloat16(v - __bfloat162float(hb));
    }
}

// ============================================================================
// Per-token 8-head local attention; emits bf16 hi/lo output + attn weights
// ============================================================================
__global__ void attn_kernel(const float* __restrict__ Q, const float* __restrict__ K,
                            const float* __restrict__ V,
                            __nv_bfloat16* __restrict__ Ohi, __nv_bfloat16* __restrict__ Olo,
                            float* __restrict__ AW)
{
    __shared__ float sq[8 * 132];
    __shared__ float sk[8 * 132];
    __shared__ float sv[8 * 132];
    __shared__ float sw[64];

    const int tid = threadIdx.x;
    const size_t base = (size_t)blockIdx.x * 1024;

    for (int i = tid; i < 1024; i += 128) {
        const int h = i >> 7, d = i & 127;
        sq[h * 132 + d] = Q[base + i];
        sk[h * 132 + d] = K[base + i];
        sv[h * 132 + d] = V[base + i];
    }
    __syncthreads();

    if (tid < 64) {
        const int h = tid >> 3, t = tid & 7;
        float s = 0.0f;
        #pragma unroll 8
        for (int d = 0; d < 128; d++)
            s += sq[h * 132 + d] * sk[t * 132 + d];
        sw[tid] = s * 0.08838834764831845f;   // 1/sqrt(128)
    }
    __syncthreads();

    if (tid < 8) {
        const int h = tid;
        float m = sw[h * 8];
        #pragma unroll
        for (int t = 1; t < 8; t++) m = fmaxf(m, sw[h * 8 + t]);
        float e[8], sum = 0.0f;
        #pragma unroll
        for (int t = 0; t < 8; t++) { e[t] = expf(sw[h * 8 + t] - m); sum += e[t]; }
        const float inv = 1.0f / sum;
        #pragma unroll
        for (int t = 0; t < 8; t++) sw[h * 8 + t] = e[t] * inv;
    }
    __syncthreads();

    const int d = tid;
    #pragma unroll
    for (int h = 0; h < 8; h++) {
        float o = 0.0f;
        #pragma unroll
        for (int t = 0; t < 8; t++)
            o += sw[h * 8 + t] * sv[t * 132 + d];
        const __nv_bfloat16 hb = __float2bfloat16(o);
        Ohi[base + h * 128 + d] = hb;
        Olo[base + h * 128 + d] = __float2bfloat16(o - __bfloat162float(hb));
    }

    if (AW != nullptr && tid < 64)
        AW[(size_t)blockIdx.x * 64 + tid] = sw[tid];
}

// ============================================================================
extern "C" void kernel_launch(void* const* d_in, const int* in_sizes, int n_in,
                              void* d_out, int out_size)
{
    (void)in_sizes; (void)n_in;
    const float* x  = (const float*)d_in[0];
    const float* W[5]  = { (const float*)d_in[1], (const float*)d_in[3],
                           (const float*)d_in[5], (const float*)d_in[7],
                           (const float*)d_in[9] };   // Wq, Wk, Wv, W1, W2
    const float* bq = (const float*)d_in[2];
    const float* bk = (const float*)d_in[4];
    const float* bv = (const float*)d_in[6];
    const float* b1 = (const float*)d_in[8];
    const float* b2 = (const float*)d_in[10];
    float* out = (float*)d_out;

    float *q, *k, *v;
    __nv_bfloat16 *xhi, *xlo, *aohi, *aolo, *hhi, *hlo, *wthi, *wtlo;
    cudaGetSymbolAddress((void**)&q,    g_q);
    cudaGetSymbolAddress((void**)&k,    g_k);
    cudaGetSymbolAddress((void**)&v,    g_v);
    cudaGetSymbolAddress((void**)&xhi,  g_xhi);
    cudaGetSymbolAddress((void**)&xlo,  g_xlo);
    cudaGetSymbolAddress((void**)&aohi, g_aohi);
    cudaGetSymbolAddress((void**)&aolo, g_aolo);
    cudaGetSymbolAddress((void**)&hhi,  g_hhi);
    cudaGetSymbolAddress((void**)&hlo,  g_hlo);
    cudaGetSymbolAddress((void**)&wthi, g_wthi);
    cudaGetSymbolAddress((void**)&wtlo, g_wtlo);

    cudaFuncSetAttribute(gemm_mma_bf16x3,
                         cudaFuncAttributeMaxDynamicSharedMemorySize, SMEM_DYN);

    const int ff_elems   = M_TOK * DM;
    const int attn_elems = M_TOK * 64;
    float* aw = (out_size >= ff_elems + attn_elems) ? (out + ff_elems) : nullptr;

    // ---- prep: split x; transpose+split weights ---------------------------
    split_kernel<<<(M_TOK * DM / 4 + 255) / 256, 256>>>(x, xhi, xlo, M_TOK * DM / 4);
    for (int i = 0; i < 5; ++i)
        wconvert_kernel<<<dim3(32, 32), dim3(32, 8)>>>(W[i],
            wthi + (size_t)i * DM * DM, wtlo + (size_t)i * DM * DM);

    dim3 grid(DM / 128, M_TOK / 128);   // (8, 128)
    dim3 block(256);

    // ---- Q/K/V projections (fp32 out) -------------------------------------
    gemm_mma_bf16x3<<<grid, block, SMEM_DYN>>>(xhi, xlo,
        wthi + 0 * (size_t)DM * DM, wtlo + 0 * (size_t)DM * DM, bq, q, nullptr, nullptr, 0);
    gemm_mma_bf16x3<<<grid, block, SMEM_DYN>>>(xhi, xlo,
        wthi + 1 * (size_t)DM * DM, wtlo + 1 * (size_t)DM * DM, bk, k, nullptr, nullptr, 0);
    gemm_mma_bf16x3<<<grid, block, SMEM_DYN>>>(xhi, xlo,
        wthi + 2 * (size_t)DM * DM, wtlo + 2 * (size_t)DM * DM, bv, v, nullptr, nullptr, 0);

    // ---- attention (emits bf16 split for FFN1) ----------------------------
    attn_kernel<<<M_TOK, 128>>>(q, k, v, aohi, aolo, aw);

    // ---- FFN --------------------------------------------------------------
    gemm_mma_bf16x3<<<grid, block, SMEM_DYN>>>(aohi, aolo,
        wthi + 3 * (size_t)DM * DM, wtlo + 3 * (size_t)DM * DM, b1, nullptr, hhi, hlo, 1);
    gemm_mma_bf16x3<<<grid, block, SMEM_DYN>>>(hhi, hlo,
        wthi + 4 * (size_t)DM * DM, wtlo + 4 * (size_t)DM * DM, b2, out, nullptr, nullptr, 0);
}